// round 16
// baseline (speedup 1.0000x reference)
#include <cuda_runtime.h>
#include <cuda_bf16.h>
#include <cuda_fp16.h>
#include <stdint.h>

// ---------------------------------------------------------------------------
// Problem constants
// ---------------------------------------------------------------------------
#define EMB   1024
#define NH    16
#define HD    64
#define BATCH 4
#define SEQ   2048
#define MROWS (BATCH*SEQ)              // 8192
#define OUT0_ELEMS (MROWS*EMB)         // 8388608  (output)
#define OUT1_ELEMS (BATCH*NH*SEQ*SEQ)  // 268435456 (attn_weights)
#define NROWS (BATCH*NH*SEQ)           // 131072 attention rows
#define NT2   (SEQ/64)                 // 32 col-tiles per row (qk v4)

// Scratch (allocation-free: __device__ globals)
__device__ __nv_bfloat16 g_xhi[MROWS*EMB];
__device__ __nv_bfloat16 g_xlo[MROWS*EMB];
__device__ __nv_bfloat16 g_wthi[4*EMB*EMB];   // transposed weights [w][n][k]
__device__ __nv_bfloat16 g_wtlo[4*EMB*EMB];
__device__ __nv_bfloat16 g_qhi[BATCH*NH*SEQ*HD];
__device__ __nv_bfloat16 g_qlo[BATCH*NH*SEQ*HD];
__device__ __nv_bfloat16 g_khi[BATCH*NH*SEQ*HD];
__device__ __nv_bfloat16 g_klo[BATCH*NH*SEQ*HD];
__device__ __half g_vh[BATCH*NH*SEQ*HD];      // V fp16 hi
__device__ __half g_vl[BATCH*NH*SEQ*HD];      // V fp16 lo (residual)
__device__ float  g_tmax[(size_t)NROWS*NT2];
__device__ float  g_tsum[(size_t)NROWS*NT2];
__device__ __half g_e[OUT1_ELEMS];            // exp(s - m_tile), fp16

// ---------------------------------------------------------------------------
// helpers
// ---------------------------------------------------------------------------
__device__ __forceinline__ uint32_t smem_u32(const void* p) {
    uint32_t a;
    asm("{ .reg .u64 t; cvta.to.shared.u64 t, %1; cvt.u32.u64 %0, t; }"
        : "=r"(a) : "l"(p));
    return a;
}
__device__ __forceinline__ void ldm_x4(uint32_t* r, uint32_t addr) {
    asm volatile("ldmatrix.sync.aligned.m8n8.x4.shared.b16 {%0,%1,%2,%3}, [%4];"
        : "=r"(r[0]), "=r"(r[1]), "=r"(r[2]), "=r"(r[3]) : "r"(addr));
}
__device__ __forceinline__ void ldm_x4_t(uint32_t* r, uint32_t addr) {
    asm volatile("ldmatrix.sync.aligned.m8n8.x4.trans.shared.b16 {%0,%1,%2,%3}, [%4];"
        : "=r"(r[0]), "=r"(r[1]), "=r"(r[2]), "=r"(r[3]) : "r"(addr));
}
__device__ __forceinline__ void mma_bf16(float* c, const uint32_t* a, const uint32_t* b) {
    asm volatile("mma.sync.aligned.m16n8k16.row.col.f32.bf16.bf16.f32 "
        "{%0,%1,%2,%3}, {%4,%5,%6,%7}, {%8,%9}, {%0,%1,%2,%3};"
        : "+f"(c[0]), "+f"(c[1]), "+f"(c[2]), "+f"(c[3])
        : "r"(a[0]), "r"(a[1]), "r"(a[2]), "r"(a[3]), "r"(b[0]), "r"(b[1]));
}
__device__ __forceinline__ void mma_f16(float* c, const uint32_t* a, const uint32_t* b) {
    asm volatile("mma.sync.aligned.m16n8k16.row.col.f32.f16.f16.f32 "
        "{%0,%1,%2,%3}, {%4,%5,%6,%7}, {%8,%9}, {%0,%1,%2,%3};"
        : "+f"(c[0]), "+f"(c[1]), "+f"(c[2]), "+f"(c[3])
        : "r"(a[0]), "r"(a[1]), "r"(a[2]), "r"(a[3]), "r"(b[0]), "r"(b[1]));
}
__device__ __forceinline__ void cp16(uint32_t saddr, const void* gaddr) {
    asm volatile("cp.async.cg.shared.global [%0], [%1], 16;" :: "r"(saddr), "l"(gaddr));
}
__device__ __forceinline__ __nv_bfloat162 hi2_of(float x, float y) {
    __nv_bfloat162 h; h.x = __float2bfloat16(x); h.y = __float2bfloat16(y);
    return h;
}
__device__ __forceinline__ __nv_bfloat162 lo2_of(float x, float y, __nv_bfloat162 h) {
    __nv_bfloat162 l;
    l.x = __float2bfloat16(x - __bfloat162float(h.x));
    l.y = __float2bfloat16(y - __bfloat162float(h.y));
    return l;
}
__device__ __forceinline__ void st_cs_b128(void* p, uint4 v) {
    asm volatile("st.global.cs.v4.b32 [%0], {%1,%2,%3,%4};"
        :: "l"(p), "r"(v.x), "r"(v.y), "r"(v.z), "r"(v.w));
}

// ---------------------------------------------------------------------------
// split kernels: fp32 -> bf16 hi/lo
// ---------------------------------------------------------------------------
__global__ void split_w(const float* __restrict__ wq, const float* __restrict__ wk,
                        const float* __restrict__ wv, const float* __restrict__ wo)
{
    __shared__ float t[32][33];
    int z = blockIdx.z;
    const float* W = (z == 0) ? wq : (z == 1) ? wk : (z == 2) ? wv : wo;
    int n0 = blockIdx.x * 32, k0 = blockIdx.y * 32;
    int tx = threadIdx.x, ty = threadIdx.y;
    t[ty][tx] = W[(size_t)(k0 + ty) * EMB + n0 + tx];
    __syncthreads();
    float v = t[tx][ty];                        // = W[k0+tx][n0+ty]
    __nv_bfloat16 hi = __float2bfloat16(v);
    __nv_bfloat16 lo = __float2bfloat16(v - __bfloat162float(hi));
    size_t o = (size_t)z * (EMB*EMB) + (size_t)(n0 + ty) * EMB + (k0 + tx);
    g_wthi[o] = hi;
    g_wtlo[o] = lo;
}

__global__ void split_x(const float* __restrict__ src)
{
    int i = (blockIdx.x * 256 + threadIdx.x) * 4;
    float4 v = *(const float4*)&src[i];
    __nv_bfloat162 hA = hi2_of(v.x, v.y);
    __nv_bfloat162 hB = hi2_of(v.z, v.w);
    *(__nv_bfloat162*)&g_xhi[i]   = hA;
    *(__nv_bfloat162*)&g_xhi[i+2] = hB;
    *(__nv_bfloat162*)&g_xlo[i]   = lo2_of(v.x, v.y, hA);
    *(__nv_bfloat162*)&g_xlo[i+2] = lo2_of(v.z, v.w, hB);
}

// ---------------------------------------------------------------------------
// HMMA 3xbf16 GEMM v3: 128x128 CTA tile, 4 warps of 64x64 (128 threads),
// KC=32 double-buffered, 2 CTAs/SM.
// qkv=1: z picks weight/bias/dst (Q scaled 1/8; V -> fp16 hi/lo); qkv=0: final.
// ---------------------------------------------------------------------------
#define KC       32
#define NCH      (EMB/KC)          // 32
#define TSTRIDE  40                // bf16 elems per smem row (80B, conflict-free)
#define TILE_B   (128*TSTRIDE*2)   // 10240 bytes
#define BUF_B    (4*TILE_B)        // Ahi, Alo, Bhi, Blo
#define GSMEM    (2*BUF_B)         // 81920

__global__ __launch_bounds__(128, 2)
void gemm_hmma(const float* __restrict__ b0, const float* __restrict__ b1,
               const float* __restrict__ b2, float* __restrict__ out, int qkv)
{
    extern __shared__ char smc[];
    uint32_t smb = smem_u32(smc);
    int tid = threadIdx.x, wid = tid >> 5, lane = tid & 31;
    int z = qkv ? blockIdx.z : 3;
    int dstmode = qkv ? (z + 1) : 0;
    const float* bias = qkv ? ((z == 0) ? b0 : (z == 1) ? b1 : b2) : b0;
    int m0 = blockIdx.y * 128, n0 = blockIdx.x * 128;
    int wm = (wid >> 1) * 64, wn = (wid & 1) * 64;

    const __nv_bfloat16* srcs[4];
    srcs[0] = g_xhi + (size_t)m0 * EMB;
    srcs[1] = g_xlo + (size_t)m0 * EMB;
    srcs[2] = g_wthi + (size_t)z * (EMB*EMB) + (size_t)n0 * EMB;
    srcs[3] = g_wtlo + (size_t)z * (EMB*EMB) + (size_t)n0 * EMB;

    float acc[4][8][4];
#pragma unroll
    for (int a = 0; a < 4; a++)
#pragma unroll
        for (int b = 0; b < 8; b++)
#pragma unroll
            for (int c = 0; c < 4; c++) acc[a][b][c] = 0.f;

#define GLD(nb, kcc) do { \
        _Pragma("unroll") \
        for (int t = 0; t < 4; t++) \
        _Pragma("unroll") \
        for (int h = 0; h < 4; h++) { \
            int s = tid + h * 128; \
            int row = s >> 2, c8 = (s & 3) * 8; \
            cp16(smb + (nb)*BUF_B + t*TILE_B + (row*TSTRIDE + c8)*2, \
                 srcs[t] + (size_t)row * EMB + (kcc)*KC + c8); \
        } \
    } while (0)

    GLD(0, 0);
    asm volatile("cp.async.commit_group;");

    int r = lane & 7, sel = lane >> 3;

    for (int kc = 0; kc < NCH; kc++) {
        int buf = kc & 1;
        if (kc + 1 < NCH) {
            GLD(buf ^ 1, kc + 1);
            asm volatile("cp.async.commit_group;");
            asm volatile("cp.async.wait_group 1;");
        } else {
            asm volatile("cp.async.wait_group 0;");
        }
        __syncthreads();

        uint32_t base = smb + buf * BUF_B;
#pragma unroll
        for (int ks = 0; ks < 2; ks++) {
            int k0 = ks * 16;
            int arow = wm + ((sel & 1) ? 8 : 0) + r;
            int acol = k0 + ((sel & 2) ? 8 : 0);
            uint32_t ah[4][4], al[4][4];
#pragma unroll
            for (int mi = 0; mi < 4; mi++) {
                uint32_t ad = base + (((arow + mi*16) * TSTRIDE + acol) * 2);
                ldm_x4(ah[mi], ad);
                ldm_x4(al[mi], ad + TILE_B);
            }
            int brow = wn + ((sel & 2) ? 8 : 0) + r;
            int bcol = k0 + ((sel & 1) ? 8 : 0);
            uint32_t bh[8][2], bl[8][2];
#pragma unroll
            for (int p = 0; p < 4; p++) {
                uint32_t t4[4];
                uint32_t bd = base + 2*TILE_B + (((brow + p*16) * TSTRIDE + bcol) * 2);
                ldm_x4(t4, bd);
                bh[p*2][0] = t4[0]; bh[p*2][1] = t4[1];
                bh[p*2+1][0] = t4[2]; bh[p*2+1][1] = t4[3];
                ldm_x4(t4, bd + TILE_B);
                bl[p*2][0] = t4[0]; bl[p*2][1] = t4[1];
                bl[p*2+1][0] = t4[2]; bl[p*2+1][1] = t4[3];
            }
#pragma unroll
            for (int mi = 0; mi < 4; mi++)
#pragma unroll
                for (int ni = 0; ni < 8; ni++) {
                    mma_bf16(acc[mi][ni], ah[mi], bh[ni]);
                    mma_bf16(acc[mi][ni], ah[mi], bl[ni]);
                    mma_bf16(acc[mi][ni], al[mi], bh[ni]);
                }
        }
        __syncthreads();
    }

    // --- epilogue ---
    int rq = lane >> 2, cq = (lane & 3) * 2;
#pragma unroll
    for (int mi = 0; mi < 4; mi++)
#pragma unroll
        for (int hh = 0; hh < 2; hh++) {
            int m = m0 + wm + mi*16 + rq + hh*8;
            int b = m >> 11, s = m & 2047;
#pragma unroll
            for (int ni = 0; ni < 8; ni++) {
                int n = n0 + wn + ni*8 + cq;
                float2 v;
                v.x = acc[mi][ni][hh*2+0] + bias[n];
                v.y = acc[mi][ni][hh*2+1] + bias[n+1];
                if (dstmode == 0) {
                    *(float2*)&out[(size_t)m*EMB + n] = v;
                } else {
                    int h = n >> 6, d = n & 63;
                    size_t idx = (((size_t)(b*NH + h)*SEQ) + s)*HD + d;
                    if (dstmode == 3) {
                        __half2 vh2 = __floats2half2_rn(v.x, v.y);
                        __half2 vl2 = __floats2half2_rn(
                            v.x - __half2float(__low2half(vh2)),
                            v.y - __half2float(__high2half(vh2)));
                        *(__half2*)&g_vh[idx] = vh2;
                        *(__half2*)&g_vl[idx] = vl2;
                    } else {
                        if (dstmode == 1) { v.x *= 0.125f; v.y *= 0.125f; }
                        __nv_bfloat16* dh = (dstmode == 1) ? g_qhi : g_khi;
                        __nv_bfloat16* dl = (dstmode == 1) ? g_qlo : g_klo;
                        __nv_bfloat162 h2 = hi2_of(v.x, v.y);
                        *(__nv_bfloat162*)&dh[idx] = h2;
                        *(__nv_bfloat162*)&dl[idx] = lo2_of(v.x, v.y, h2);
                    }
                }
            }
        }
}

// ---------------------------------------------------------------------------
// qk_hmma v4: 128x64 S tile per 128-thread CTA (4 warps of 64x32), 54 KB smem
// -> 4 CTAs/SM. Same epilogue pipeline as R15 (max -> single-exp+sum -> 
// coalesced e-store), tiles now 64 wide (NT2=32 per row).
// ---------------------------------------------------------------------------
#define QKSTR  72
#define QTILE  (128*QKSTR*2)   // 18432 (one of Qhi/Qlo)
#define KTILE  (64*QKSTR*2)    // 9216  (one of Khi/Klo)
#define QKSMEM (2*QTILE + 2*KTILE)  // 55296
#define ESTR   72              // halfs per e-staging row

__global__ __launch_bounds__(128, 4)
void qk_hmma()
{
    extern __shared__ char smc[];
    __shared__ float mtrow[128];
    uint32_t smb = smem_u32(smc);
    int tid = threadIdx.x, wid = tid >> 5, lane = tid & 31;
    int bh = blockIdx.z;
    int m0 = blockIdx.y * 128, n0 = blockIdx.x * 64;
    int wm = (wid >> 1) * 64, wn = (wid & 1) * 32;

    const __nv_bfloat16* Qh = g_qhi + ((size_t)bh*SEQ + m0) * HD;
    const __nv_bfloat16* Ql = g_qlo + ((size_t)bh*SEQ + m0) * HD;
    const __nv_bfloat16* Kh = g_khi + ((size_t)bh*SEQ + n0) * HD;
    const __nv_bfloat16* Kl = g_klo + ((size_t)bh*SEQ + n0) * HD;

#pragma unroll
    for (int t = 0; t < 2; t++)
#pragma unroll
        for (int i = 0; i < 8; i++) {
            int u = tid + i * 128;
            int row = u >> 3, c8 = (u & 7) * 8;
            cp16(smb + t*QTILE + (row*QKSTR + c8)*2,
                 (t ? Ql : Qh) + (size_t)row*HD + c8);
        }
#pragma unroll
    for (int t = 0; t < 2; t++)
#pragma unroll
        for (int i = 0; i < 4; i++) {
            int u = tid + i * 128;
            int row = u >> 3, c8 = (u & 7) * 8;
            cp16(smb + 2*QTILE + t*KTILE + (row*QKSTR + c8)*2,
                 (t ? Kl : Kh) + (size_t)row*HD + c8);
        }
    asm volatile("cp.async.commit_group;");
    asm volatile("cp.async.wait_group 0;");
    __syncthreads();

    float acc[4][4][4];
#pragma unroll
    for (int a = 0; a < 4; a++)
#pragma unroll
        for (int b = 0; b < 4; b++)
#pragma unroll
            for (int c = 0; c < 4; c++) acc[a][b][c] = 0.f;

    int r = lane & 7, sel = lane >> 3;
#pragma unroll
    for (int ks = 0; ks < 4; ks++) {
        int k0 = ks * 16;
        int arow = wm + ((sel & 1) ? 8 : 0) + r;
        int acol = k0 + ((sel & 2) ? 8 : 0);
        uint32_t ah[4][4], al[4][4];
#pragma unroll
        for (int mi = 0; mi < 4; mi++) {
            uint32_t ad = smb + (((arow + mi*16) * QKSTR + acol) * 2);
            ldm_x4(ah[mi], ad);
            ldm_x4(al[mi], ad + QTILE);
        }
        int brow = wn + ((sel & 2) ? 8 : 0) + r;
        int bcol = k0 + ((sel & 1) ? 8 : 0);
        uint32_t bh[4][2], bl[4][2];
#pragma unroll
        for (int p = 0; p < 2; p++) {
            uint32_t t4[4];
            uint32_t bd = smb + 2*QTILE + (((brow + p*16) * QKSTR + bcol) * 2);
            ldm_x4(t4, bd);
            bh[p*2][0] = t4[0]; bh[p*2][1] = t4[1];
            bh[p*2+1][0] = t4[2]; bh[p*2+1][1] = t4[3];
            ldm_x4(t4, bd + KTILE);
            bl[p*2][0] = t4[0]; bl[p*2][1] = t4[1];
            bl[p*2+1][0] = t4[2]; bl[p*2+1][1] = t4[3];
        }
#pragma unroll
        for (int mi = 0; mi < 4; mi++)
#pragma unroll
            for (int ni = 0; ni < 4; ni++) {
                mma_bf16(acc[mi][ni], ah[mi], bh[ni]);
                mma_bf16(acc[mi][ni], ah[mi], bl[ni]);
                mma_bf16(acc[mi][ni], al[mi], bh[ni]);
            }
    }

    int rq = lane >> 2, cq = (lane & 3) * 2;
    int wq2 = wid & 1;

    // ---- pass 1: row-tile max ----
    __syncthreads();                      // tile smem reads done; reuse smc
    float* st = (float*)smc;              // [128 rows][2 groups]
#pragma unroll
    for (int mi = 0; mi < 4; mi++)
#pragma unroll
        for (int hh = 0; hh < 2; hh++) {
            float m8 = -1e30f;
#pragma unroll
            for (int ni = 0; ni < 4; ni++)
                m8 = fmaxf(m8, fmaxf(acc[mi][ni][hh*2+0], acc[mi][ni][hh*2+1]));
            m8 = fmaxf(m8, __shfl_xor_sync(0xffffffffu, m8, 1));
            m8 = fmaxf(m8, __shfl_xor_sync(0xffffffffu, m8, 2));
            if ((lane & 3) == 0) {
                int rl = wm + mi*16 + rq + hh*8;
                st[rl*2 + wq2] = m8;
            }
        }
    __syncthreads();
    if (tid < 128) {
        mtrow[tid] = fmaxf(st[tid*2+0], st[tid*2+1]);
    }
    __syncthreads();

    // ---- pass 2: e = exp(s - mt) once -> smem e-tile + tile sums ----
    float* st2 = (float*)(smc + 2048);          // [128 rows][2 groups] sums
    __half* es = (__half*)(smc + 4096);         // [128][ESTR] staging
#pragma unroll
    for (int mi = 0; mi < 4; mi++)
#pragma unroll
        for (int hh = 0; hh < 2; hh++) {
            int mloc = wm + mi*16 + rq + hh*8;
            float mt = mtrow[mloc];
            float s8 = 0.f;
#pragma unroll
            for (int ni = 0; ni < 4; ni++) {
                int nl = wn + ni*8 + cq;
                float e0 = __expf(acc[mi][ni][hh*2+0] - mt);
                float e1 = __expf(acc[mi][ni][hh*2+1] - mt);
                s8 += e0 + e1;
                *(__half2*)&es[mloc*ESTR + nl] = __floats2half2_rn(e0, e1);
            }
            s8 += __shfl_xor_sync(0xffffffffu, s8, 1);
            s8 += __shfl_xor_sync(0xffffffffu, s8, 2);
            if ((lane & 3) == 0)
                st2[mloc*2 + wq2] = s8;
        }
    __syncthreads();
    if (tid < 128) {
        float s = st2[tid*2+0] + st2[tid*2+1];
        size_t o = ((size_t)bh*SEQ + m0 + tid) * NT2 + blockIdx.x;
        g_tmax[o] = mtrow[tid];
        g_tsum[o] = s;
    }

    // ---- pass 3: coalesced 16B streaming stores of the e-tile ----
    __half* Ep = g_e + (size_t)bh * SEQ * SEQ + n0;
#pragma unroll
    for (int i = 0; i < 8; i++) {
        int u = tid + i * 128;
        int row = u >> 3, ch = (u & 7) * 8;
        uint4 v = *(uint4*)&es[row*ESTR + ch];
        st_cs_b128(Ep + (size_t)(m0 + row)*SEQ + ch, v);
    }
}

// ---------------------------------------------------------------------------
// pv_hmma: builds sc[row][tile64] = exp(m_t - gmax)/sum; streams fp16 e into
// smem via cp.async, writes fp32 P = e*sc to attn_weights (streaming),
// and computes O = e @ (Vh + Vl) fp16 MMA with per-tile fp32 rescale.
// Writes merged attn output to g_xhi/g_xlo for the final projection.
// ---------------------------------------------------------------------------
#define PVSTR  72
#define PTILE  (128*PVSTR*2)        // 18432 (e tile, fp16, 64 cols used)
#define VTILE  (64*PVSTR*2)         // 9216
#define PVBUF  (PTILE + 2*VTILE)    // 36864
#define PVSMEM (2*PVBUF)            // 73728
#define PVNCH  (SEQ/64)             // 32

__global__ __launch_bounds__(256)
void pv_hmma(float* __restrict__ P, int hasP)
{
    extern __shared__ char smc[];
    __shared__ float sc[128][NT2];
    uint32_t smb = smem_u32(smc);
    int tid = threadIdx.x, wid = tid >> 5, lane = tid & 31;
    int bh = blockIdx.y;
    int m0 = blockIdx.x * 128;
    int wm = (wid >> 2) * 64, wn = (wid & 3) * 16;

    float* Pp = P + ((size_t)bh*SEQ + m0) * SEQ;
    const __half* Ep = g_e + ((size_t)bh*SEQ + m0) * SEQ;
    const __half* Vh = g_vh + (size_t)bh * SEQ * HD;
    const __half* Vl = g_vl + (size_t)bh * SEQ * HD;

    // per-row scale table (rowstat combine folded in)
    if (tid < 128) {
        size_t o = ((size_t)bh*SEQ + m0 + tid) * NT2;
        float m = -1e30f;
#pragma unroll 8
        for (int t = 0; t < NT2; t++) m = fmaxf(m, g_tmax[o + t]);
        float s = 0.f;
#pragma unroll 8
        for (int t = 0; t < NT2; t++) s += g_tsum[o + t] * __expf(g_tmax[o + t] - m);
        float inv = 1.f / s;
#pragma unroll 8
        for (int t = 0; t < NT2; t++) sc[tid][t] = __expf(g_tmax[o + t] - m) * inv;
    }
    __syncthreads();

    float out[4][2][4];
#pragma unroll
    for (int a = 0; a < 4; a++)
#pragma unroll
        for (int b = 0; b < 2; b++)
#pragma unroll
            for (int c = 0; c < 4; c++) out[a][b][c] = 0.f;

#define PV_LOAD(nb, cc) do { \
        _Pragma("unroll") \
        for (int i = 0; i < 4; i++) { \
            int u = tid + i * 256; \
            int row = u >> 3, c8 = (u & 7) * 8; \
            cp16(smb + (nb)*PVBUF + (row*PVSTR + c8)*2, \
                 Ep + (size_t)row*SEQ + (cc)*64 + c8); \
        } \
        _Pragma("unroll") \
        for (int i = 0; i < 2; i++) { \
            int u = tid + i * 256; \
            int row = u >> 3, c8 = (u & 7) * 8; \
            const __half* vsrc = Vh + (size_t)((cc)*64 + row)*HD + c8; \
            cp16(smb + (nb)*PVBUF + PTILE + (row*PVSTR + c8)*2, vsrc); \
            const __half* vsrc2 = Vl + (size_t)((cc)*64 + row)*HD + c8; \
            cp16(smb + (nb)*PVBUF + PTILE + VTILE + (row*PVSTR + c8)*2, vsrc2); \
        } \
    } while (0)

    PV_LOAD(0, 0);
    asm volatile("cp.async.commit_group;");

    int r = lane & 7, sel = lane >> 3;
    int rq = lane >> 2, cq = (lane & 3) * 2;

    for (int c = 0; c < PVNCH; c++) {
        int buf = c & 1;
        asm volatile("cp.async.wait_group 0;");
        __syncthreads();

        if (c + 1 < PVNCH) {
            PV_LOAD(buf ^ 1, c + 1);
            asm volatile("cp.async.commit_group;");
        }

        uint32_t pbase = smb + buf * PVBUF;

        // ---- fp32 P write from smem e ----
        if (hasP) {
            float* Pc = Pp + c*64;
#pragma unroll
            for (int i = 0; i < 8; i++) {
                int u = tid + i * 256;
                int row = u >> 4, h4 = (u & 15) * 4;
                uint2 e2 = *(uint2*)(smc + buf*PVBUF + (row*PVSTR + h4)*2);
                float scr = sc[row][c];
                __half2 ea = *(__half2*)&e2.x;
                __half2 eb = *(__half2*)&e2.y;
                float4 p;
                p.x = __half2float(__low2half(ea)) * scr;
                p.y = __half2float(__high2half(ea)) * scr;
                p.z = __half2float(__low2half(eb)) * scr;
                p.w = __half2float(__high2half(eb)) * scr;
                __stcs((float4*)&Pc[(size_t)row*SEQ + h4], p);
            }
        }

        // ---- fp16 MMA: part = e @ (Vh + Vl) ----
        float part[4][2][4];
#pragma unroll
        for (int a = 0; a < 4; a++)
#pragma unroll
            for (int b = 0; b < 2; b++)
#pragma unroll
                for (int d = 0; d < 4; d++) part[a][b][d] = 0.f;

#pragma unroll
        for (int ks = 0; ks < 4; ks++) {
            int k0 = ks * 16;
            int arow = wm + ((sel & 1) ? 8 : 0) + r;
            int acol = k0 + ((sel & 2) ? 8 : 0);
            uint32_t ap[4][4];
#pragma unroll
            for (int mi = 0; mi < 4; mi++)
                ldm_x4(ap[mi], pbase + (((arow + mi*16) * PVSTR + acol) * 2));

            int krow = k0 + ((sel & 1) ? 8 : 0) + r;
            int ncol = wn + ((sel & 2) ? 8 : 0);
            uint32_t bhf[2][2], blf[2][2], t4[4];
            uint32_t bd = pbase + PTILE + ((krow * PVSTR + ncol) * 2);
            ldm_x4_t(t4, bd);
            bhf[0][0] = t4[0]; bhf[0][1] = t4[1];
            bhf[1][0] = t4[2]; bhf[1][1] = t4[3];
            ldm_x4_t(t4, bd + VTILE);
            blf[0][0] = t4[0]; blf[0][1] = t4[1];
            blf[1][0] = t4[2]; blf[1][1] = t4[3];
#pragma unroll
            for (int mi = 0; mi < 4; mi++)
#pragma unroll
                for (int ni = 0; ni < 2; ni++) {
                    mma_f16(part[mi][ni], ap[mi], bhf[ni]);
                    mma_f16(part[mi][ni], ap[mi], blf[ni]);
                }
        }

        // ---- rescale partials by per-(row, tile) softmax scale ----
#pragma unroll
        for (int mi = 0; mi < 4; mi++)
#pragma unroll
            for (int hh = 0; hh < 2; hh++) {
                int row = wm + mi*16 + rq + hh*8;
                float s_ = sc[row][c];
#pragma unroll
                for (int ni = 0; ni < 2; ni++) {
                    out[mi][ni][hh*2+0] += s_ * part[mi][ni][hh*2+0];
                    out[mi][ni][hh*2+1] += s_ * part[mi][ni][hh*2+1];
                }
            }
    }

    // ---- epilogue: merged attn output as bf16 hi/lo for final GEMM ----
    int b = bh >> 4, h = bh & 15;
#pragma unroll
    for (int mi = 0; mi < 4; mi++)
#pragma unroll
        for (int hh = 0; hh < 2; hh++) {
            int s = m0 + wm + mi*16 + rq + hh*8;
#pragma unroll
            for (int ni = 0; ni < 2; ni++) {
                int d = wn + ni*8 + cq;
                float vx = out[mi][ni][hh*2+0];
                float vy = out[mi][ni][hh*2+1];
                size_t idx = ((size_t)(b*SEQ + s))*EMB + h*HD + d;
                __nv_bfloat162 h2 = hi2_of(vx, vy);
                *(__nv_bfloat162*)&g_xhi[idx] = h2;
                *(__nv_bfloat162*)&g_xlo[idx] = lo2_of(vx, vy, h2);
            }
        }
}

// ---------------------------------------------------------------------------
extern "C" void kernel_launch(void* const* d_in, const int* in_sizes, int n_in,
                              void* d_out, int out_size)
{
    const float* x  = (const float*)d_in[0];
    const float* bq = (const float*)d_in[5];
    const float* bk = (const float*)d_in[6];
    const float* bv = (const float*)d_in[7];
    const float* bo = (const float*)d_in[8];
    float* out = (float*)d_out;

    int hasAttnW = (out_size >= (OUT0_ELEMS + OUT1_ELEMS)) ? 1 : 0;
    float* attnW = hasAttnW ? (out + OUT0_ELEMS) : out;

    cudaFuncSetAttribute(gemm_hmma,
                         cudaFuncAttributeMaxDynamicSharedMemorySize, GSMEM);
    cudaFuncSetAttribute(qk_hmma,
                         cudaFuncAttributeMaxDynamicSharedMemorySize, QKSMEM);
    cudaFuncSetAttribute(pv_hmma,
                         cudaFuncAttributeMaxDynamicSharedMemorySize, PVSMEM);

    // Split weights (transposed) and x into bf16 hi/lo
    split_w<<<dim3(32, 32, 4), dim3(32, 32)>>>(
        (const float*)d_in[1], (const float*)d_in[2],
        (const float*)d_in[3], (const float*)d_in[4]);
    split_x<<<MROWS*EMB/(256*4), 256>>>(x);

    // QKV projections: one z-merged launch, 128x128 tiles, 4-warp CTAs
    gemm_hmma<<<dim3(EMB/128, MROWS/128, 3), 128, GSMEM>>>(bq, bk, bv, (float*)0, 1);

    qk_hmma<<<dim3(SEQ/64, SEQ/128, BATCH*NH), 128, QKSMEM>>>();
    pv_hmma<<<dim3(SEQ/128, BATCH*NH), 256, PVSMEM>>>(attnW, hasAttnW);

    // Output projection
    gemm_hmma<<<dim3(EMB/128, MROWS/128, 1), 128, GSMEM>>>(bo, bo, bo, out, 0);
}

// round 17
// speedup vs baseline: 1.0319x; 1.0319x over previous
#include <cuda_runtime.h>
#include <cuda_bf16.h>
#include <cuda_fp16.h>
#include <stdint.h>

// ---------------------------------------------------------------------------
// Problem constants
// ---------------------------------------------------------------------------
#define EMB   1024
#define NH    16
#define HD    64
#define BATCH 4
#define SEQ   2048
#define MROWS (BATCH*SEQ)              // 8192
#define OUT0_ELEMS (MROWS*EMB)         // 8388608  (output)
#define OUT1_ELEMS (BATCH*NH*SEQ*SEQ)  // 268435456 (attn_weights)
#define NROWS (BATCH*NH*SEQ)           // 131072 attention rows
#define NT2   (SEQ/64)                 // 32 col-tiles per row

// Scratch (allocation-free: __device__ globals)
__device__ __nv_bfloat16 g_xhi[MROWS*EMB];
__device__ __nv_bfloat16 g_xlo[MROWS*EMB];
__device__ __nv_bfloat16 g_wthi[4*EMB*EMB];   // transposed weights [w][n][k]
__device__ __nv_bfloat16 g_wtlo[4*EMB*EMB];
__device__ __nv_bfloat16 g_qhi[BATCH*NH*SEQ*HD];
__device__ __nv_bfloat16 g_qlo[BATCH*NH*SEQ*HD];
__device__ __nv_bfloat16 g_khi[BATCH*NH*SEQ*HD];
__device__ __nv_bfloat16 g_klo[BATCH*NH*SEQ*HD];
__device__ __half g_vh[BATCH*NH*SEQ*HD];      // V fp16 hi
__device__ __half g_vl[BATCH*NH*SEQ*HD];      // V fp16 lo (residual)
__device__ float  g_tmax[(size_t)NROWS*NT2];
__device__ float  g_tsum[(size_t)NROWS*NT2];
__device__ __half g_e[OUT1_ELEMS];            // exp(s - m_tile), fp16

// ---------------------------------------------------------------------------
// helpers
// ---------------------------------------------------------------------------
__device__ __forceinline__ uint32_t smem_u32(const void* p) {
    uint32_t a;
    asm("{ .reg .u64 t; cvta.to.shared.u64 t, %1; cvt.u32.u64 %0, t; }"
        : "=r"(a) : "l"(p));
    return a;
}
__device__ __forceinline__ void ldm_x4(uint32_t* r, uint32_t addr) {
    asm volatile("ldmatrix.sync.aligned.m8n8.x4.shared.b16 {%0,%1,%2,%3}, [%4];"
        : "=r"(r[0]), "=r"(r[1]), "=r"(r[2]), "=r"(r[3]) : "r"(addr));
}
__device__ __forceinline__ void ldm_x4_t(uint32_t* r, uint32_t addr) {
    asm volatile("ldmatrix.sync.aligned.m8n8.x4.trans.shared.b16 {%0,%1,%2,%3}, [%4];"
        : "=r"(r[0]), "=r"(r[1]), "=r"(r[2]), "=r"(r[3]) : "r"(addr));
}
__device__ __forceinline__ void mma_bf16(float* c, const uint32_t* a, const uint32_t* b) {
    asm volatile("mma.sync.aligned.m16n8k16.row.col.f32.bf16.bf16.f32 "
        "{%0,%1,%2,%3}, {%4,%5,%6,%7}, {%8,%9}, {%0,%1,%2,%3};"
        : "+f"(c[0]), "+f"(c[1]), "+f"(c[2]), "+f"(c[3])
        : "r"(a[0]), "r"(a[1]), "r"(a[2]), "r"(a[3]), "r"(b[0]), "r"(b[1]));
}
__device__ __forceinline__ void mma_f16(float* c, const uint32_t* a, const uint32_t* b) {
    asm volatile("mma.sync.aligned.m16n8k16.row.col.f32.f16.f16.f32 "
        "{%0,%1,%2,%3}, {%4,%5,%6,%7}, {%8,%9}, {%0,%1,%2,%3};"
        : "+f"(c[0]), "+f"(c[1]), "+f"(c[2]), "+f"(c[3])
        : "r"(a[0]), "r"(a[1]), "r"(a[2]), "r"(a[3]), "r"(b[0]), "r"(b[1]));
}
__device__ __forceinline__ void cp16(uint32_t saddr, const void* gaddr) {
    asm volatile("cp.async.cg.shared.global [%0], [%1], 16;" :: "r"(saddr), "l"(gaddr));
}
__device__ __forceinline__ __nv_bfloat162 hi2_of(float x, float y) {
    __nv_bfloat162 h; h.x = __float2bfloat16(x); h.y = __float2bfloat16(y);
    return h;
}
__device__ __forceinline__ __nv_bfloat162 lo2_of(float x, float y, __nv_bfloat162 h) {
    __nv_bfloat162 l;
    l.x = __float2bfloat16(x - __bfloat162float(h.x));
    l.y = __float2bfloat16(y - __bfloat162float(h.y));
    return l;
}
__device__ __forceinline__ void st_cs_b128(void* p, uint4 v) {
    asm volatile("st.global.cs.v4.b32 [%0], {%1,%2,%3,%4};"
        :: "l"(p), "r"(v.x), "r"(v.y), "r"(v.z), "r"(v.w));
}

// ---------------------------------------------------------------------------
// split kernels: fp32 -> bf16 hi/lo
// ---------------------------------------------------------------------------
__global__ void split_w(const float* __restrict__ wq, const float* __restrict__ wk,
                        const float* __restrict__ wv, const float* __restrict__ wo)
{
    __shared__ float t[32][33];
    int z = blockIdx.z;
    const float* W = (z == 0) ? wq : (z == 1) ? wk : (z == 2) ? wv : wo;
    int n0 = blockIdx.x * 32, k0 = blockIdx.y * 32;
    int tx = threadIdx.x, ty = threadIdx.y;
    t[ty][tx] = W[(size_t)(k0 + ty) * EMB + n0 + tx];
    __syncthreads();
    float v = t[tx][ty];                        // = W[k0+tx][n0+ty]
    __nv_bfloat16 hi = __float2bfloat16(v);
    __nv_bfloat16 lo = __float2bfloat16(v - __bfloat162float(hi));
    size_t o = (size_t)z * (EMB*EMB) + (size_t)(n0 + ty) * EMB + (k0 + tx);
    g_wthi[o] = hi;
    g_wtlo[o] = lo;
}

__global__ void split_x(const float* __restrict__ src)
{
    int i = (blockIdx.x * 256 + threadIdx.x) * 4;
    float4 v = *(const float4*)&src[i];
    __nv_bfloat162 hA = hi2_of(v.x, v.y);
    __nv_bfloat162 hB = hi2_of(v.z, v.w);
    *(__nv_bfloat162*)&g_xhi[i]   = hA;
    *(__nv_bfloat162*)&g_xhi[i+2] = hB;
    *(__nv_bfloat162*)&g_xlo[i]   = lo2_of(v.x, v.y, hA);
    *(__nv_bfloat162*)&g_xlo[i+2] = lo2_of(v.z, v.w, hB);
}

// ---------------------------------------------------------------------------
// HMMA 3xbf16 GEMM v3: 128x128 CTA tile, 4 warps of 64x64 (128 threads),
// KC=32 double-buffered, 2 CTAs/SM.
// qkv=1: z picks weight/bias/dst (Q scaled 1/8; V -> fp16 hi/lo); qkv=0: final.
// ---------------------------------------------------------------------------
#define KC       32
#define NCH      (EMB/KC)          // 32
#define TSTRIDE  40                // bf16 elems per smem row (80B, conflict-free)
#define TILE_B   (128*TSTRIDE*2)   // 10240 bytes
#define BUF_B    (4*TILE_B)        // Ahi, Alo, Bhi, Blo
#define GSMEM    (2*BUF_B)         // 81920

__global__ __launch_bounds__(128, 2)
void gemm_hmma(const float* __restrict__ b0, const float* __restrict__ b1,
               const float* __restrict__ b2, float* __restrict__ out, int qkv)
{
    extern __shared__ char smc[];
    uint32_t smb = smem_u32(smc);
    int tid = threadIdx.x, wid = tid >> 5, lane = tid & 31;
    int z = qkv ? blockIdx.z : 3;
    int dstmode = qkv ? (z + 1) : 0;
    const float* bias = qkv ? ((z == 0) ? b0 : (z == 1) ? b1 : b2) : b0;
    int m0 = blockIdx.y * 128, n0 = blockIdx.x * 128;
    int wm = (wid >> 1) * 64, wn = (wid & 1) * 64;

    const __nv_bfloat16* srcs[4];
    srcs[0] = g_xhi + (size_t)m0 * EMB;
    srcs[1] = g_xlo + (size_t)m0 * EMB;
    srcs[2] = g_wthi + (size_t)z * (EMB*EMB) + (size_t)n0 * EMB;
    srcs[3] = g_wtlo + (size_t)z * (EMB*EMB) + (size_t)n0 * EMB;

    float acc[4][8][4];
#pragma unroll
    for (int a = 0; a < 4; a++)
#pragma unroll
        for (int b = 0; b < 8; b++)
#pragma unroll
            for (int c = 0; c < 4; c++) acc[a][b][c] = 0.f;

#define GLD(nb, kcc) do { \
        _Pragma("unroll") \
        for (int t = 0; t < 4; t++) \
        _Pragma("unroll") \
        for (int h = 0; h < 4; h++) { \
            int s = tid + h * 128; \
            int row = s >> 2, c8 = (s & 3) * 8; \
            cp16(smb + (nb)*BUF_B + t*TILE_B + (row*TSTRIDE + c8)*2, \
                 srcs[t] + (size_t)row * EMB + (kcc)*KC + c8); \
        } \
    } while (0)

    GLD(0, 0);
    asm volatile("cp.async.commit_group;");

    int r = lane & 7, sel = lane >> 3;

    for (int kc = 0; kc < NCH; kc++) {
        int buf = kc & 1;
        if (kc + 1 < NCH) {
            GLD(buf ^ 1, kc + 1);
            asm volatile("cp.async.commit_group;");
            asm volatile("cp.async.wait_group 1;");
        } else {
            asm volatile("cp.async.wait_group 0;");
        }
        __syncthreads();

        uint32_t base = smb + buf * BUF_B;
#pragma unroll
        for (int ks = 0; ks < 2; ks++) {
            int k0 = ks * 16;
            int arow = wm + ((sel & 1) ? 8 : 0) + r;
            int acol = k0 + ((sel & 2) ? 8 : 0);
            uint32_t ah[4][4], al[4][4];
#pragma unroll
            for (int mi = 0; mi < 4; mi++) {
                uint32_t ad = base + (((arow + mi*16) * TSTRIDE + acol) * 2);
                ldm_x4(ah[mi], ad);
                ldm_x4(al[mi], ad + TILE_B);
            }
            int brow = wn + ((sel & 2) ? 8 : 0) + r;
            int bcol = k0 + ((sel & 1) ? 8 : 0);
            uint32_t bh[8][2], bl[8][2];
#pragma unroll
            for (int p = 0; p < 4; p++) {
                uint32_t t4[4];
                uint32_t bd = base + 2*TILE_B + (((brow + p*16) * TSTRIDE + bcol) * 2);
                ldm_x4(t4, bd);
                bh[p*2][0] = t4[0]; bh[p*2][1] = t4[1];
                bh[p*2+1][0] = t4[2]; bh[p*2+1][1] = t4[3];
                ldm_x4(t4, bd + TILE_B);
                bl[p*2][0] = t4[0]; bl[p*2][1] = t4[1];
                bl[p*2+1][0] = t4[2]; bl[p*2+1][1] = t4[3];
            }
#pragma unroll
            for (int mi = 0; mi < 4; mi++)
#pragma unroll
                for (int ni = 0; ni < 8; ni++) {
                    mma_bf16(acc[mi][ni], ah[mi], bh[ni]);
                    mma_bf16(acc[mi][ni], ah[mi], bl[ni]);
                    mma_bf16(acc[mi][ni], al[mi], bh[ni]);
                }
        }
        __syncthreads();
    }

    // --- epilogue ---
    int rq = lane >> 2, cq = (lane & 3) * 2;
#pragma unroll
    for (int mi = 0; mi < 4; mi++)
#pragma unroll
        for (int hh = 0; hh < 2; hh++) {
            int m = m0 + wm + mi*16 + rq + hh*8;
            int b = m >> 11, s = m & 2047;
#pragma unroll
            for (int ni = 0; ni < 8; ni++) {
                int n = n0 + wn + ni*8 + cq;
                float2 v;
                v.x = acc[mi][ni][hh*2+0] + bias[n];
                v.y = acc[mi][ni][hh*2+1] + bias[n+1];
                if (dstmode == 0) {
                    *(float2*)&out[(size_t)m*EMB + n] = v;
                } else {
                    int h = n >> 6, d = n & 63;
                    size_t idx = (((size_t)(b*NH + h)*SEQ) + s)*HD + d;
                    if (dstmode == 3) {
                        __half2 vh2 = __floats2half2_rn(v.x, v.y);
                        __half2 vl2 = __floats2half2_rn(
                            v.x - __half2float(__low2half(vh2)),
                            v.y - __half2float(__high2half(vh2)));
                        *(__half2*)&g_vh[idx] = vh2;
                        *(__half2*)&g_vl[idx] = vl2;
                    } else {
                        if (dstmode == 1) { v.x *= 0.125f; v.y *= 0.125f; }
                        __nv_bfloat16* dh = (dstmode == 1) ? g_qhi : g_khi;
                        __nv_bfloat16* dl = (dstmode == 1) ? g_qlo : g_klo;
                        __nv_bfloat162 h2 = hi2_of(v.x, v.y);
                        *(__nv_bfloat162*)&dh[idx] = h2;
                        *(__nv_bfloat162*)&dl[idx] = lo2_of(v.x, v.y, h2);
                    }
                }
            }
        }
}

// ---------------------------------------------------------------------------
// qk_hmma v4: 128x64 S tile per 128-thread CTA (4 warps of 64x32), 54 KB smem
// -> 4 CTAs/SM. Epilogue: max -> single-exp+sum -> coalesced e-store.
// ---------------------------------------------------------------------------
#define QKSTR  72
#define QTILE  (128*QKSTR*2)   // 18432 (one of Qhi/Qlo)
#define KTILE  (64*QKSTR*2)    // 9216  (one of Khi/Klo)
#define QKSMEM (2*QTILE + 2*KTILE)  // 55296
#define ESTR   72              // halfs per e-staging row

__global__ __launch_bounds__(128, 4)
void qk_hmma()
{
    extern __shared__ char smc[];
    __shared__ float mtrow[128];
    uint32_t smb = smem_u32(smc);
    int tid = threadIdx.x, wid = tid >> 5, lane = tid & 31;
    int bh = blockIdx.z;
    int m0 = blockIdx.y * 128, n0 = blockIdx.x * 64;
    int wm = (wid >> 1) * 64, wn = (wid & 1) * 32;

    const __nv_bfloat16* Qh = g_qhi + ((size_t)bh*SEQ + m0) * HD;
    const __nv_bfloat16* Ql = g_qlo + ((size_t)bh*SEQ + m0) * HD;
    const __nv_bfloat16* Kh = g_khi + ((size_t)bh*SEQ + n0) * HD;
    const __nv_bfloat16* Kl = g_klo + ((size_t)bh*SEQ + n0) * HD;

#pragma unroll
    for (int t = 0; t < 2; t++)
#pragma unroll
        for (int i = 0; i < 8; i++) {
            int u = tid + i * 128;
            int row = u >> 3, c8 = (u & 7) * 8;
            cp16(smb + t*QTILE + (row*QKSTR + c8)*2,
                 (t ? Ql : Qh) + (size_t)row*HD + c8);
        }
#pragma unroll
    for (int t = 0; t < 2; t++)
#pragma unroll
        for (int i = 0; i < 4; i++) {
            int u = tid + i * 128;
            int row = u >> 3, c8 = (u & 7) * 8;
            cp16(smb + 2*QTILE + t*KTILE + (row*QKSTR + c8)*2,
                 (t ? Kl : Kh) + (size_t)row*HD + c8);
        }
    asm volatile("cp.async.commit_group;");
    asm volatile("cp.async.wait_group 0;");
    __syncthreads();

    float acc[4][4][4];
#pragma unroll
    for (int a = 0; a < 4; a++)
#pragma unroll
        for (int b = 0; b < 4; b++)
#pragma unroll
            for (int c = 0; c < 4; c++) acc[a][b][c] = 0.f;

    int r = lane & 7, sel = lane >> 3;
#pragma unroll
    for (int ks = 0; ks < 4; ks++) {
        int k0 = ks * 16;
        int arow = wm + ((sel & 1) ? 8 : 0) + r;
        int acol = k0 + ((sel & 2) ? 8 : 0);
        uint32_t ah[4][4], al[4][4];
#pragma unroll
        for (int mi = 0; mi < 4; mi++) {
            uint32_t ad = smb + (((arow + mi*16) * QKSTR + acol) * 2);
            ldm_x4(ah[mi], ad);
            ldm_x4(al[mi], ad + QTILE);
        }
        int brow = wn + ((sel & 2) ? 8 : 0) + r;
        int bcol = k0 + ((sel & 1) ? 8 : 0);
        uint32_t bh[4][2], bl[4][2];
#pragma unroll
        for (int p = 0; p < 2; p++) {
            uint32_t t4[4];
            uint32_t bd = smb + 2*QTILE + (((brow + p*16) * QKSTR + bcol) * 2);
            ldm_x4(t4, bd);
            bh[p*2][0] = t4[0]; bh[p*2][1] = t4[1];
            bh[p*2+1][0] = t4[2]; bh[p*2+1][1] = t4[3];
            ldm_x4(t4, bd + KTILE);
            bl[p*2][0] = t4[0]; bl[p*2][1] = t4[1];
            bl[p*2+1][0] = t4[2]; bl[p*2+1][1] = t4[3];
        }
#pragma unroll
        for (int mi = 0; mi < 4; mi++)
#pragma unroll
            for (int ni = 0; ni < 4; ni++) {
                mma_bf16(acc[mi][ni], ah[mi], bh[ni]);
                mma_bf16(acc[mi][ni], ah[mi], bl[ni]);
                mma_bf16(acc[mi][ni], al[mi], bh[ni]);
            }
    }

    int rq = lane >> 2, cq = (lane & 3) * 2;
    int wq2 = wid & 1;

    // ---- pass 1: row-tile max ----
    __syncthreads();                      // tile smem reads done; reuse smc
    float* st = (float*)smc;              // [128 rows][2 groups]
#pragma unroll
    for (int mi = 0; mi < 4; mi++)
#pragma unroll
        for (int hh = 0; hh < 2; hh++) {
            float m8 = -1e30f;
#pragma unroll
            for (int ni = 0; ni < 4; ni++)
                m8 = fmaxf(m8, fmaxf(acc[mi][ni][hh*2+0], acc[mi][ni][hh*2+1]));
            m8 = fmaxf(m8, __shfl_xor_sync(0xffffffffu, m8, 1));
            m8 = fmaxf(m8, __shfl_xor_sync(0xffffffffu, m8, 2));
            if ((lane & 3) == 0) {
                int rl = wm + mi*16 + rq + hh*8;
                st[rl*2 + wq2] = m8;
            }
        }
    __syncthreads();
    if (tid < 128) {
        mtrow[tid] = fmaxf(st[tid*2+0], st[tid*2+1]);
    }
    __syncthreads();

    // ---- pass 2: e = exp(s - mt) once -> smem e-tile + tile sums ----
    float* st2 = (float*)(smc + 2048);          // [128 rows][2 groups] sums
    __half* es = (__half*)(smc + 4096);         // [128][ESTR] staging
#pragma unroll
    for (int mi = 0; mi < 4; mi++)
#pragma unroll
        for (int hh = 0; hh < 2; hh++) {
            int mloc = wm + mi*16 + rq + hh*8;
            float mt = mtrow[mloc];
            float s8 = 0.f;
#pragma unroll
            for (int ni = 0; ni < 4; ni++) {
                int nl = wn + ni*8 + cq;
                float e0 = __expf(acc[mi][ni][hh*2+0] - mt);
                float e1 = __expf(acc[mi][ni][hh*2+1] - mt);
                s8 += e0 + e1;
                *(__half2*)&es[mloc*ESTR + nl] = __floats2half2_rn(e0, e1);
            }
            s8 += __shfl_xor_sync(0xffffffffu, s8, 1);
            s8 += __shfl_xor_sync(0xffffffffu, s8, 2);
            if ((lane & 3) == 0)
                st2[mloc*2 + wq2] = s8;
        }
    __syncthreads();
    if (tid < 128) {
        float s = st2[tid*2+0] + st2[tid*2+1];
        size_t o = ((size_t)bh*SEQ + m0 + tid) * NT2 + blockIdx.x;
        g_tmax[o] = mtrow[tid];
        g_tsum[o] = s;
    }

    // ---- pass 3: coalesced 16B streaming stores of the e-tile ----
    __half* Ep = g_e + (size_t)bh * SEQ * SEQ + n0;
#pragma unroll
    for (int i = 0; i < 8; i++) {
        int u = tid + i * 128;
        int row = u >> 3, ch = (u & 7) * 8;
        uint4 v = *(uint4*)&es[row*ESTR + ch];
        st_cs_b128(Ep + (size_t)(m0 + row)*SEQ + ch, v);
    }
}

// ---------------------------------------------------------------------------
// pv_hmma: builds sc[row][tile64] = exp(m_t - gmax)/sum (parallel over 256
// threads, float4 stat loads); streams fp16 e into smem via cp.async,
// writes fp32 P = e*sc to attn_weights (streaming), and computes
// O = e @ (Vh + Vl) fp16 MMA with per-tile fp32 rescale.
// ---------------------------------------------------------------------------
#define PVSTR  72
#define PTILE  (128*PVSTR*2)        // 18432 (e tile, fp16, 64 cols used)
#define VTILE  (64*PVSTR*2)         // 9216
#define PVBUF  (PTILE + 2*VTILE)    // 36864
#define PVSMEM (2*PVBUF)            // 73728
#define PVNCH  (SEQ/64)             // 32

__global__ __launch_bounds__(256)
void pv_hmma(float* __restrict__ P, int hasP)
{
    extern __shared__ char smc[];
    __shared__ float sc[128][NT2];
    __shared__ float2 ps[256];
    uint32_t smb = smem_u32(smc);
    int tid = threadIdx.x, wid = tid >> 5, lane = tid & 31;
    int bh = blockIdx.y;
    int m0 = blockIdx.x * 128;
    int wm = (wid >> 2) * 64, wn = (wid & 3) * 16;

    float* Pp = P + ((size_t)bh*SEQ + m0) * SEQ;
    const __half* Ep = g_e + ((size_t)bh*SEQ + m0) * SEQ;
    const __half* Vh = g_vh + (size_t)bh * SEQ * HD;
    const __half* Vl = g_vl + (size_t)bh * SEQ * HD;

    // ---- parallel scale-table build: 2 threads per row, 16 tiles each ----
    {
        int row = tid & 127, half = tid >> 7;
        size_t o = ((size_t)bh*SEQ + m0 + row) * NT2 + half * 16;
        float tm[16], ts[16];
#pragma unroll
        for (int q = 0; q < 4; q++) {
            *(float4*)&tm[q*4] = *(const float4*)&g_tmax[o + q*4];
            *(float4*)&ts[q*4] = *(const float4*)&g_tsum[o + q*4];
        }
        float m = -1e30f;
#pragma unroll
        for (int t = 0; t < 16; t++) m = fmaxf(m, tm[t]);
        float s = 0.f;
#pragma unroll
        for (int t = 0; t < 16; t++) s += ts[t] * __expf(tm[t] - m);
        ps[tid] = make_float2(m, s);
        __syncthreads();
        float2 a = ps[row], b2 = ps[row + 128];
        float gm = fmaxf(a.x, b2.x);
        float gs = a.y * __expf(a.x - gm) + b2.y * __expf(b2.x - gm);
        float inv = 1.f / gs;
#pragma unroll
        for (int t = 0; t < 16; t++)
            sc[row][half*16 + t] = __expf(tm[t] - gm) * inv;
    }
    __syncthreads();

    float out[4][2][4];
#pragma unroll
    for (int a = 0; a < 4; a++)
#pragma unroll
        for (int b = 0; b < 2; b++)
#pragma unroll
            for (int c = 0; c < 4; c++) out[a][b][c] = 0.f;

#define PV_LOAD(nb, cc) do { \
        _Pragma("unroll") \
        for (int i = 0; i < 4; i++) { \
            int u = tid + i * 256; \
            int row = u >> 3, c8 = (u & 7) * 8; \
            cp16(smb + (nb)*PVBUF + (row*PVSTR + c8)*2, \
                 Ep + (size_t)row*SEQ + (cc)*64 + c8); \
        } \
        _Pragma("unroll") \
        for (int i = 0; i < 2; i++) { \
            int u = tid + i * 256; \
            int row = u >> 3, c8 = (u & 7) * 8; \
            const __half* vsrc = Vh + (size_t)((cc)*64 + row)*HD + c8; \
            cp16(smb + (nb)*PVBUF + PTILE + (row*PVSTR + c8)*2, vsrc); \
            const __half* vsrc2 = Vl + (size_t)((cc)*64 + row)*HD + c8; \
            cp16(smb + (nb)*PVBUF + PTILE + VTILE + (row*PVSTR + c8)*2, vsrc2); \
        } \
    } while (0)

    PV_LOAD(0, 0);
    asm volatile("cp.async.commit_group;");

    int r = lane & 7, sel = lane >> 3;
    int rq = lane >> 2, cq = (lane & 3) * 2;

    for (int c = 0; c < PVNCH; c++) {
        int buf = c & 1;
        asm volatile("cp.async.wait_group 0;");
        __syncthreads();

        if (c + 1 < PVNCH) {
            PV_LOAD(buf ^ 1, c + 1);
            asm volatile("cp.async.commit_group;");
        }

        uint32_t pbase = smb + buf * PVBUF;

        // ---- fp32 P write from smem e ----
        if (hasP) {
            float* Pc = Pp + c*64;
#pragma unroll
            for (int i = 0; i < 8; i++) {
                int u = tid + i * 256;
                int row = u >> 4, h4 = (u & 15) * 4;
                uint2 e2 = *(uint2*)(smc + buf*PVBUF + (row*PVSTR + h4)*2);
                float scr = sc[row][c];
                __half2 ea = *(__half2*)&e2.x;
                __half2 eb = *(__half2*)&e2.y;
                float4 p;
                p.x = __half2float(__low2half(ea)) * scr;
                p.y = __half2float(__high2half(ea)) * scr;
                p.z = __half2float(__low2half(eb)) * scr;
                p.w = __half2float(__high2half(eb)) * scr;
                __stcs((float4*)&Pc[(size_t)row*SEQ + h4], p);
            }
        }

        // ---- fp16 MMA: part = e @ (Vh + Vl) ----
        float part[4][2][4];
#pragma unroll
        for (int a = 0; a < 4; a++)
#pragma unroll
            for (int b = 0; b < 2; b++)
#pragma unroll
                for (int d = 0; d < 4; d++) part[a][b][d] = 0.f;

#pragma unroll
        for (int ks = 0; ks < 4; ks++) {
            int k0 = ks * 16;
            int arow = wm + ((sel & 1) ? 8 : 0) + r;
            int acol = k0 + ((sel & 2) ? 8 : 0);
            uint32_t ap[4][4];
#pragma unroll
            for (int mi = 0; mi < 4; mi++)
                ldm_x4(ap[mi], pbase + (((arow + mi*16) * PVSTR + acol) * 2));

            int krow = k0 + ((sel & 1) ? 8 : 0) + r;
            int ncol = wn + ((sel & 2) ? 8 : 0);
            uint32_t bhf[2][2], blf[2][2], t4[4];
            uint32_t bd = pbase + PTILE + ((krow * PVSTR + ncol) * 2);
            ldm_x4_t(t4, bd);
            bhf[0][0] = t4[0]; bhf[0][1] = t4[1];
            bhf[1][0] = t4[2]; bhf[1][1] = t4[3];
            ldm_x4_t(t4, bd + VTILE);
            blf[0][0] = t4[0]; blf[0][1] = t4[1];
            blf[1][0] = t4[2]; blf[1][1] = t4[3];
#pragma unroll
            for (int mi = 0; mi < 4; mi++)
#pragma unroll
                for (int ni = 0; ni < 2; ni++) {
                    mma_f16(part[mi][ni], ap[mi], bhf[ni]);
                    mma_f16(part[mi][ni], ap[mi], blf[ni]);
                }
        }

        // ---- rescale partials by per-(row, tile) softmax scale ----
#pragma unroll
        for (int mi = 0; mi < 4; mi++)
#pragma unroll
            for (int hh = 0; hh < 2; hh++) {
                int row = wm + mi*16 + rq + hh*8;
                float s_ = sc[row][c];
#pragma unroll
                for (int ni = 0; ni < 2; ni++) {
                    out[mi][ni][hh*2+0] += s_ * part[mi][ni][hh*2+0];
                    out[mi][ni][hh*2+1] += s_ * part[mi][ni][hh*2+1];
                }
            }
    }

    // ---- epilogue: merged attn output as bf16 hi/lo for final GEMM ----
    int b = bh >> 4, h = bh & 15;
#pragma unroll
    for (int mi = 0; mi < 4; mi++)
#pragma unroll
        for (int hh = 0; hh < 2; hh++) {
            int s = m0 + wm + mi*16 + rq + hh*8;
#pragma unroll
            for (int ni = 0; ni < 2; ni++) {
                int d = wn + ni*8 + cq;
                float vx = out[mi][ni][hh*2+0];
                float vy = out[mi][ni][hh*2+1];
                size_t idx = ((size_t)(b*SEQ + s))*EMB + h*HD + d;
                __nv_bfloat162 h2 = hi2_of(vx, vy);
                *(__nv_bfloat162*)&g_xhi[idx] = h2;
                *(__nv_bfloat162*)&g_xlo[idx] = lo2_of(vx, vy, h2);
            }
        }
}

// ---------------------------------------------------------------------------
extern "C" void kernel_launch(void* const* d_in, const int* in_sizes, int n_in,
                              void* d_out, int out_size)
{
    const float* x  = (const float*)d_in[0];
    const float* bq = (const float*)d_in[5];
    const float* bk = (const float*)d_in[6];
    const float* bv = (const float*)d_in[7];
    const float* bo = (const float*)d_in[8];
    float* out = (float*)d_out;

    int hasAttnW = (out_size >= (OUT0_ELEMS + OUT1_ELEMS)) ? 1 : 0;
    float* attnW = hasAttnW ? (out + OUT0_ELEMS) : out;

    cudaFuncSetAttribute(gemm_hmma,
                         cudaFuncAttributeMaxDynamicSharedMemorySize, GSMEM);
    cudaFuncSetAttribute(qk_hmma,
                         cudaFuncAttributeMaxDynamicSharedMemorySize, QKSMEM);
    cudaFuncSetAttribute(pv_hmma,
                         cudaFuncAttributeMaxDynamicSharedMemorySize, PVSMEM);

    // Split weights (transposed) and x into bf16 hi/lo
    split_w<<<dim3(32, 32, 4), dim3(32, 32)>>>(
        (const float*)d_in[1], (const float*)d_in[2],
        (const float*)d_in[3], (const float*)d_in[4]);
    split_x<<<MROWS*EMB/(256*4), 256>>>(x);

    // QKV projections: one z-merged launch, 128x128 tiles, 4-warp CTAs
    gemm_hmma<<<dim3(EMB/128, MROWS/128, 3), 128, GSMEM>>>(bq, bk, bv, (float*)0, 1);

    qk_hmma<<<dim3(SEQ/64, SEQ/128, BATCH*NH), 128, QKSMEM>>>();
    pv_hmma<<<dim3(SEQ/128, BATCH*NH), 256, PVSMEM>>>(attnW, hasAttnW);

    // Output projection
    gemm_hmma<<<dim3(EMB/128, MROWS/128, 1), 128, GSMEM>>>(bo, bo, bo, out, 0);
}